// round 13
// baseline (speedup 1.0000x reference)
#include <cuda_runtime.h>
#include <cuda_fp16.h>
#include <cstdint>

// ---------------- problem constants ----------------
#define B_    8
#define C_    1024
#define H_    48
#define P_    (H_*H_)        // 2304
#define HP_   24
#define P2_   (HP_*HP_)      // 576
#define POS4_ (P2_*P2_)      // 331776
#define EPS_L2 1e-6f
#define EPS_MM 1e-5f

// ---------------- scratch (device globals) ----------------
__device__ __half g_faN[B_*P_*C_];   // normalized A, fp16, [b][p][c] K-major
__device__ __half g_fbN[B_*P_*C_];   // normalized B, fp16
__device__ float g_corr[B_*P_*P_];
__device__ float g_pool[B_*P2_*P2_];
__device__ float g_amax[B_*P2_];
__device__ float g_bmax[B_*P2_];
__device__ float g_c1[B_*10*POS4_];
__device__ float g_c2[B_*10*POS4_];
__device__ float g_x3[B_*POS4_];

// ---------------- PTX helpers ----------------
__device__ __forceinline__ uint32_t smem_u32(const void* p) {
    uint32_t a;
    asm("{ .reg .u64 t; cvta.to.shared.u64 t, %1; cvt.u32.u64 %0, t; }" : "=r"(a) : "l"(p));
    return a;
}
__device__ __forceinline__ void ldsm_x4(uint32_t* r, uint32_t addr) {
    asm volatile("ldmatrix.sync.aligned.m8n8.x4.shared.b16 {%0,%1,%2,%3}, [%4];"
        : "=r"(r[0]), "=r"(r[1]), "=r"(r[2]), "=r"(r[3]) : "r"(addr));
}
__device__ __forceinline__ void mma_f16(float* d, const uint32_t* a, uint32_t b0, uint32_t b1) {
    asm volatile("mma.sync.aligned.m16n8k16.row.col.f32.f16.f16.f32 "
        "{%0,%1,%2,%3}, {%4,%5,%6,%7}, {%8,%9}, {%0,%1,%2,%3};"
        : "+f"(d[0]), "+f"(d[1]), "+f"(d[2]), "+f"(d[3])
        : "r"(a[0]), "r"(a[1]), "r"(a[2]), "r"(a[3]), "r"(b0), "r"(b1));
}
__device__ __forceinline__ void cp16(uint32_t sdst, const void* g) {
    asm volatile("cp.async.cg.shared.global [%0], [%1], 16;" :: "r"(sdst), "l"(g));
}
#define CP_COMMIT() asm volatile("cp.async.commit_group;" ::: "memory")
#define CP_WAIT(n)  asm volatile("cp.async.wait_group %0;" :: "n"(n) : "memory")

// ---------------- 1) L2 norm + transpose -> fp16 K-major ----------------
__global__ void l2norm_half(const float* __restrict__ f, __half* __restrict__ o) {
    int tx = threadIdx.x, ty = threadIdx.y;   // (32, 8)
    int p0 = blockIdx.x * 32;
    int b  = blockIdx.y;
    const float* src = f + (size_t)b * C_ * P_;
    float s = 0.f;
    for (int c = ty; c < C_; c += 8) {
        float v = src[(size_t)c * P_ + p0 + tx];
        s += v * v;
    }
    __shared__ float red[8][33];
    __shared__ float inv[32];
    red[ty][tx] = s;
    __syncthreads();
    if (ty == 0) {
        float t = 0.f;
        #pragma unroll
        for (int r = 0; r < 8; r++) t += red[r][tx];
        inv[tx] = rsqrtf(t + EPS_L2);
    }
    __shared__ float tile[32][33];
    __half* ob = o + (size_t)b * P_ * C_;
    for (int c0 = 0; c0 < C_; c0 += 32) {
        __syncthreads();
        #pragma unroll
        for (int r = 0; r < 4; r++) {
            int c = c0 + ty + r * 8;
            tile[ty + r * 8][tx] = src[(size_t)c * P_ + p0 + tx];
        }
        __syncthreads();
        #pragma unroll
        for (int r = 0; r < 4; r++) {
            int pl = ty + r * 8;
            float v = tile[tx][pl] * inv[pl];
            ob[(size_t)(p0 + pl) * C_ + c0 + tx] = __float2half_rn(v);
        }
    }
}

// ---------------- 2) correlation GEMM via mma.sync fp16, K-chunk 64 ----------------
// corr[p][q] = sum_c a[p][c]*b[q][c]; fused relu + x*rsqrt(x^2+eps).
// CTA 128x128, 256 threads, warp tile 32x64. K chunk 64, cp.async double buffer.
#define KCH   64
#define NCHNK (C_ / KCH)          // 16
#define ROWB  144                 // 128B data + 16B pad -> conflict-free ldmatrix
#define OPB   (128 * ROWB)        // 18432 per operand tile
#define STAGE (2 * OPB)           // A, B = 36864
#define DYNSM (2 * STAGE)         // 73728 -> 2 CTAs/SM (needs attr opt-in)

__global__ void __launch_bounds__(256, 2) corr_gemm_mma(
    const __half* __restrict__ A, const __half* __restrict__ B,
    float* __restrict__ Co) {
    extern __shared__ __align__(128) char dynsm[];
    uint32_t sb = smem_u32(dynsm);

    int b = blockIdx.z;
    int pBase = blockIdx.y * 128;
    int qBase = blockIdx.x * 128;

    int tid  = threadIdx.x;
    int lane = tid & 31;
    int wid  = tid >> 5;
    int mBase = (wid & 3) * 32;
    int nBase = (wid >> 2) * 64;

    // ---- load mapping: op = tid&1 (A or B), row lr = tid>>1 (0..127), 8x16B per chunk row
    int op = tid & 1;
    int lr = tid >> 1;
    const __half* gb = op ? (B + ((size_t)b * P_ + qBase) * C_)
                          : (A + ((size_t)b * P_ + pBase) * C_);
    const char* gRow = (const char*)gb + (size_t)lr * (C_ * 2);
    uint32_t sRow = sb + op * OPB + lr * ROWB;

    float acc[2][8][4];
    #pragma unroll
    for (int mi = 0; mi < 2; mi++)
        #pragma unroll
        for (int ni = 0; ni < 8; ni++)
            #pragma unroll
            for (int e = 0; e < 4; e++) acc[mi][ni][e] = 0.f;

    // ---- ldmatrix address components (row*ROWB + 16B-column select)
    uint32_t aOff = (uint32_t)((mBase + (lane & 15)) * ROWB + (lane >> 4) * 16);
    uint32_t bOff = (uint32_t)((nBase + (lane & 7) + ((lane >> 4) << 3)) * ROWB + ((lane >> 3) & 1) * 16);

    // ---- prologue: chunk 0 -> buf 0
    {
        #pragma unroll
        for (int c = 0; c < 8; c++) cp16(sRow + c * 16, gRow + c * 16);
        CP_COMMIT();
    }

    for (int s = 0; s < NCHNK; s++) {
        int buf = s & 1;
        if (s + 1 < NCHNK) {
            int nb = (s + 1) & 1;
            const char* g0 = gRow + (size_t)(s + 1) * (KCH * 2);   // bytes
            uint32_t s0 = sRow + nb * STAGE;
            #pragma unroll
            for (int c = 0; c < 8; c++) cp16(s0 + c * 16, g0 + c * 16);
            CP_COMMIT();
            CP_WAIT(1);
        } else {
            CP_WAIT(0);
        }
        __syncthreads();

        uint32_t stg = sb + buf * STAGE;
        #pragma unroll
        for (int ks = 0; ks < 4; ks++) {
            uint32_t ah[2][4], bh[4][4];
            #pragma unroll
            for (int mi = 0; mi < 2; mi++)
                ldsm_x4(ah[mi], stg + aOff + mi * 16 * ROWB + ks * 32);
            #pragma unroll
            for (int ni = 0; ni < 4; ni++)
                ldsm_x4(bh[ni], stg + OPB + bOff + ni * 16 * ROWB + ks * 32);
            #pragma unroll
            for (int mi = 0; mi < 2; mi++)
                #pragma unroll
                for (int ni = 0; ni < 4; ni++)
                    #pragma unroll
                    for (int h = 0; h < 2; h++)
                        mma_f16(acc[mi][ni * 2 + h], ah[mi], bh[ni][h * 2], bh[ni][h * 2 + 1]);
        }
        __syncthreads();
    }

    // ---- epilogue: relu + x*rsqrt(x^2+eps), float2 stores
    float* Cb = Co + (size_t)b * P_ * P_;
    #pragma unroll
    for (int mi = 0; mi < 2; mi++) {
        int r0 = pBase + mBase + mi * 16 + (lane >> 2);
        #pragma unroll
        for (int ni = 0; ni < 8; ni++) {
            int c0 = qBase + nBase + ni * 8 + (lane & 3) * 2;
            float v0 = acc[mi][ni][0], v1 = acc[mi][ni][1];
            float v2 = acc[mi][ni][2], v3 = acc[mi][ni][3];
            v0 = v0 > 0.f ? v0 : 0.f;  v1 = v1 > 0.f ? v1 : 0.f;
            v2 = v2 > 0.f ? v2 : 0.f;  v3 = v3 > 0.f ? v3 : 0.f;
            float2 o0 = make_float2(v0 * rsqrtf(v0 * v0 + EPS_L2), v1 * rsqrtf(v1 * v1 + EPS_L2));
            float2 o1 = make_float2(v2 * rsqrtf(v2 * v2 + EPS_L2), v3 * rsqrtf(v3 * v3 + EPS_L2));
            *(float2*)(Cb + (size_t)r0 * P_ + c0)       = o0;
            *(float2*)(Cb + (size_t)(r0 + 8) * P_ + c0) = o1;
        }
    }
}

// ---------------- 3) 4D max pool k=2 ----------------
__global__ void maxpool_kernel(const float* __restrict__ c, float* __restrict__ out) {
    int idx = blockIdx.x * 256 + threadIdx.x;
    const int N = B_ * POS4_;
    if (idx >= N) return;
    int l = idx % HP_;       int t = idx / HP_;
    int k = t % HP_;         t /= HP_;
    int j = t % HP_;         t /= HP_;
    int i = t % HP_;         int b = t / HP_;
    const float* base = c + (size_t)b * P_ * P_;
    float m = 0.f;
    #pragma unroll
    for (int di = 0; di < 2; di++)
        #pragma unroll
        for (int dj = 0; dj < 2; dj++) {
            int p = (2 * i + di) * H_ + 2 * j + dj;
            const float* row = base + (size_t)p * P_;
            #pragma unroll
            for (int dk = 0; dk < 2; dk++)
                #pragma unroll
                for (int dl = 0; dl < 2; dl++)
                    m = fmaxf(m, row[(2 * k + dk) * H_ + 2 * l + dl]);
        }
    out[idx] = m;
}

// ---------------- 4) mutual matching helpers ----------------
__global__ void rowmax_kernel(const float* __restrict__ x, float* __restrict__ out) {
    int row = blockIdx.x * 8 + threadIdx.y;
    const float* r = x + (size_t)row * P2_;
    float m = -1e30f;
    for (int q = threadIdx.x; q < P2_; q += 32) m = fmaxf(m, r[q]);
    #pragma unroll
    for (int o = 16; o; o >>= 1) m = fmaxf(m, __shfl_xor_sync(0xffffffffu, m, o));
    if (threadIdx.x == 0) out[row] = m;
}
__global__ void colmax_kernel(const float* __restrict__ x, float* __restrict__ out) {
    int b = blockIdx.y;
    int q = blockIdx.x * 64 + threadIdx.x;
    const float* base = x + (size_t)b * P2_ * P2_ + q;
    float m = -1e30f;
    #pragma unroll 8
    for (int p = 0; p < P2_; p++) m = fmaxf(m, base[(size_t)p * P2_]);
    out[b * P2_ + q] = m;
}
__global__ void mm_kernel(const float* __restrict__ x, const float* __restrict__ amax,
                          const float* __restrict__ bmax, float* __restrict__ out) {
    int idx = blockIdx.x * 256 + threadIdx.x;
    const int N = B_ * POS4_;
    if (idx >= N) return;
    int q2 = idx % P2_;
    int t  = idx / P2_;
    int p2 = t % P2_;
    int b  = t / P2_;
    float v  = x[idx];
    float t1 = v / (amax[b * P2_ + p2] + EPS_MM);
    float t2 = v / (bmax[b * P2_ + q2] + EPS_MM);
    out[idx] = v * t1 * t2;
}

// ---------------- 5) conv4d (3x3x3x3, SAME, +bias, +relu), scalar fp32 ----------------
template<int CIN, int COUT>
__global__ void __launch_bounds__(144) conv4d_kernel(const float* __restrict__ x,
                                                     const float* __restrict__ w,
                                                     const float* __restrict__ bias,
                                                     float* __restrict__ y) {
    int b  = blockIdx.y;
    int ij = blockIdx.x;
    int i = ij / HP_, j = ij % HP_;
    int tx = threadIdx.x;
    int ty = threadIdx.y;
    int tid = ty * 24 + tx;
    int k0 = ty * 4;

    __shared__ float sw[COUT * CIN * 81];
    __shared__ float sx[26][27];

    for (int idx = tid; idx < COUT * CIN * 81; idx += 144) sw[idx] = w[idx];

    float acc[COUT][4];
    #pragma unroll
    for (int co = 0; co < COUT; co++) {
        float bv = bias[co];
        #pragma unroll
        for (int kk = 0; kk < 4; kk++) acc[co][kk] = bv;
    }

    for (int ci = 0; ci < CIN; ci++) {
        const float* xc = x + (size_t)(b * CIN + ci) * POS4_;
        #pragma unroll
        for (int di = 0; di < 3; di++) {
            int ii = i + di - 1;
            #pragma unroll
            for (int dj = 0; dj < 3; dj++) {
                int jj = j + dj - 1;
                __syncthreads();
                bool valid = (ii >= 0) && (ii < HP_) && (jj >= 0) && (jj < HP_);
                const float* plane = xc + (size_t)(ii * HP_ + jj) * P2_;
                for (int idx = tid; idx < 26 * 26; idx += 144) {
                    int kk = idx / 26, ll = idx % 26;
                    int ks = kk - 1, ls = ll - 1;
                    float v = 0.f;
                    if (valid && ks >= 0 && ks < HP_ && ls >= 0 && ls < HP_)
                        v = plane[ks * HP_ + ls];
                    sx[kk][ll] = v;
                }
                __syncthreads();
                float xr[6][3];
                #pragma unroll
                for (int r = 0; r < 6; r++)
                    #pragma unroll
                    for (int c2 = 0; c2 < 3; c2++)
                        xr[r][c2] = sx[k0 + r][tx + c2];
                #pragma unroll
                for (int co = 0; co < COUT; co++) {
                    const float* wp = &sw[((co * CIN + ci) * 9 + di * 3 + dj) * 9];
                    float wr[9];
                    #pragma unroll
                    for (int t = 0; t < 9; t++) wr[t] = wp[t];
                    #pragma unroll
                    for (int kk = 0; kk < 4; kk++)
                        #pragma unroll
                        for (int dk = 0; dk < 3; dk++)
                            #pragma unroll
                            for (int dl = 0; dl < 3; dl++)
                                acc[co][kk] += xr[kk + dk][dl] * wr[dk * 3 + dl];
                }
            }
        }
    }
    size_t posbase = (size_t)(i * HP_ + j) * P2_ + tx;
    #pragma unroll
    for (int co = 0; co < COUT; co++) {
        float* yo = y + (size_t)(b * COUT + co) * POS4_ + posbase;
        #pragma unroll
        for (int kk = 0; kk < 4; kk++) {
            float v = acc[co][kk];
            yo[(k0 + kk) * HP_] = v > 0.f ? v : 0.f;
        }
    }
}

// ---------------- launch ----------------
extern "C" void kernel_launch(void* const* d_in, const int* in_sizes, int n_in,
                              void* d_out, int out_size) {
    const float* fA = (const float*)d_in[0];
    const float* fB = (const float*)d_in[1];
    const float* w1 = (const float*)d_in[2];
    const float* b1 = (const float*)d_in[3];
    const float* w2 = (const float*)d_in[4];
    const float* b2 = (const float*)d_in[5];
    const float* w3 = (const float*)d_in[6];
    const float* b3 = (const float*)d_in[7];
    float* out = (float*)d_out;

    __half *faN, *fbN;
    float *corr, *pool, *amax, *bmax, *c1, *c2, *x3;
    cudaGetSymbolAddress((void**)&faN,  g_faN);
    cudaGetSymbolAddress((void**)&fbN,  g_fbN);
    cudaGetSymbolAddress((void**)&corr, g_corr);
    cudaGetSymbolAddress((void**)&pool, g_pool);
    cudaGetSymbolAddress((void**)&amax, g_amax);
    cudaGetSymbolAddress((void**)&bmax, g_bmax);
    cudaGetSymbolAddress((void**)&c1,   g_c1);
    cudaGetSymbolAddress((void**)&c2,   g_c2);
    cudaGetSymbolAddress((void**)&x3,   g_x3);

    // 1) normalize + transpose to fp16 K-major
    dim3 nb(P_ / 32, B_), nt(32, 8);
    l2norm_half<<<nb, nt>>>(fA, faN);
    l2norm_half<<<nb, nt>>>(fB, fbN);

    // 2) correlation on mma.sync fp16 tensor cores (72KB dynsmem -> opt-in)
    cudaFuncSetAttribute(corr_gemm_mma, cudaFuncAttributeMaxDynamicSharedMemorySize, DYNSM);
    corr_gemm_mma<<<dim3(P_ / 128, P_ / 128, B_), 256, DYNSM>>>(faN, fbN, corr);

    // 3) 4D maxpool
    const int NP = B_ * POS4_;
    maxpool_kernel<<<(NP + 255) / 256, 256>>>(corr, pool);

    // 4) mutual matching (in place)
    rowmax_kernel<<<(B_ * P2_) / 8, dim3(32, 8)>>>(pool, amax);
    colmax_kernel<<<dim3(P2_ / 64, B_), 64>>>(pool, bmax);
    mm_kernel<<<(NP + 255) / 256, 256>>>(pool, amax, bmax, pool);

    // 5) neighbourhood consensus convs (scalar fp32)
    dim3 cg(P2_, B_), cb(24, 6);
    conv4d_kernel<1, 10><<<cg, cb>>>(pool, w1, b1, c1);
    conv4d_kernel<10, 10><<<cg, cb>>>(c1, w2, b2, c2);
    conv4d_kernel<10, 1><<<cg, cb>>>(c2, w3, b3, x3);

    // 6) final mutual matching -> output
    rowmax_kernel<<<(B_ * P2_) / 8, dim3(32, 8)>>>(x3, amax);
    colmax_kernel<<<dim3(P2_ / 64, B_), 64>>>(x3, bmax);
    mm_kernel<<<(NP + 255) / 256, 256>>>(x3, amax, bmax, out);
}